// round 4
// baseline (speedup 1.0000x reference)
#include <cuda_runtime.h>
#include <math.h>

// Router gate: probs = softmax(h @ W^T * scale + bias), top-8 (weights, indices).
// T=16384, D=2048, E=64. fp32 exact via f32x2 FFMA, blocked (DK=32) accumulation.
// R4: grid 512 (TM=32) for 3-4 warps/SMSP, dup-stored h (LDS.64, no MOVs).

#define TDIM 2048
#define NEXP 64
#define TOPK 8
#define TM   32           // tokens per CTA  -> grid = 512
#define DK   32           // k-chunk
#define NTH  128          // 8 expert-threads x 16 token-threads
#define HP2  33           // h smem row stride in float2 (pad)
#define WP   66           // w smem row stride (experts, pad 2, 8B-aligned pairs)
#define WOFF (TM * HP2 * 2)             // 2112 floats (h region = [TM][HP2] float2)
#define SMEM_FLOATS (WOFF + DK * WP)    // 2112 + 2112 = 4224 floats

typedef unsigned long long u64t;

__device__ __forceinline__ void fma_f32x2(u64t& c, u64t a, u64t b) {
    asm("fma.rn.f32x2 %0, %1, %2, %0;" : "+l"(c) : "l"(a), "l"(b));
}
__device__ __forceinline__ u64t mul_f32x2(u64t a, u64t b) {
    u64t r;
    asm("mul.rn.f32x2 %0, %1, %2;" : "=l"(r) : "l"(a), "l"(b));
    return r;
}
__device__ __forceinline__ u64t add_f32x2(u64t a, u64t b) {
    u64t r;
    asm("add.rn.f32x2 %0, %1, %2;" : "=l"(r) : "l"(a), "l"(b));
    return r;
}
__device__ __forceinline__ void unpack_f32x2(u64t v, float& lo, float& hi) {
    unsigned int l, h;
    asm("mov.b64 {%0, %1}, %2;" : "=r"(l), "=r"(h) : "l"(v));
    lo = __uint_as_float(l);
    hi = __uint_as_float(h);
}

// top-8 insertion, jax.lax.top_k semantics: descending, ties -> smaller index
// first. Strict '>' on entry and bubble-up gives exactly that.
#define TOPK_INSERT(p, e)                                              \
    do {                                                               \
        if ((p) > tv[7]) {                                             \
            tv[7] = (p); tix[7] = (e);                                 \
            _Pragma("unroll")                                          \
            for (int _r = 7; _r > 0; _r--) {                           \
                if (tv[_r] > tv[_r - 1]) {                             \
                    float _tv = tv[_r]; tv[_r] = tv[_r-1]; tv[_r-1] = _tv; \
                    int   _ti = tix[_r]; tix[_r] = tix[_r-1]; tix[_r-1] = _ti; \
                }                                                      \
            }                                                          \
        }                                                              \
    } while (0)

__global__ __launch_bounds__(NTH, 4)
void router_gate_kernel(const float* __restrict__ hs,
                        const float* __restrict__ rw,
                        const float* __restrict__ cs,
                        const float* __restrict__ cb,
                        float* __restrict__ out,
                        int T)
{
    __shared__ __align__(16) float sm[SMEM_FLOATS];
    __shared__ float s_cs[NEXP], s_cb[NEXP];

    const int tid = threadIdx.x;
    const int tx  = tid & 7;    // expert pairs (2tx+16j, 2tx+16j+1), j=0..3
    const int ty  = tid >> 3;   // tokens ty + 16*i, i=0..1
    const int t0  = blockIdx.x * TM;
    const float* hblk = hs + (long long)t0 * TDIM;
    float2* h2 = reinterpret_cast<float2*>(sm);

    if (tid < NEXP) { s_cs[tid] = cs[tid]; s_cb[tid] = cb[tid]; }

    // totals + per-chunk accumulators (packed f32x2: expert pair per reg-pair)
    u64t acc[2][4];
    #pragma unroll
    for (int i = 0; i < 2; i++)
        #pragma unroll
        for (int j = 0; j < 4; j++) acc[i][j] = 0ull;

    float4 ph[2];   // h chunk prefetch: 32x32 floats = 2 float4/thread
    float4 pw[4];   // w chunk prefetch: 64x32 floats = 4 float4/thread

    const int hk4  = (tid & 7) * 4;   // k offset (8 lanes cover a 128B row)
    const int hrow = tid >> 3;        // 0..15, rows hrow + 16p

    auto loadg = [&](int kc) {
        #pragma unroll
        for (int p = 0; p < 2; p++) {
            int r = hrow + 16 * p;
            ph[p] = *reinterpret_cast<const float4*>(hblk + r * TDIM + kc + hk4);
        }
        #pragma unroll
        for (int q = 0; q < 4; q++) {
            int fid = tid + NTH * q;        // 0..511
            int e   = fid >> 3;             // expert 0..63
            int kv  = fid & 7;              // k-quad
            pw[q] = *reinterpret_cast<const float4*>(rw + e * TDIM + kc + kv * 4);
        }
    };

    auto sts = [&]() {
        #pragma unroll
        for (int p = 0; p < 2; p++) {
            int r = hrow + 16 * p;
            float2* dst = &h2[r * HP2 + hk4];
            dst[0] = make_float2(ph[p].x, ph[p].x);   // duplicated pair -> LDS.64
            dst[1] = make_float2(ph[p].y, ph[p].y);
            dst[2] = make_float2(ph[p].z, ph[p].z);
            dst[3] = make_float2(ph[p].w, ph[p].w);
        }
        // w transposed: w_s[k][e] so expert pairs are contiguous (LDS.64)
        #pragma unroll
        for (int q = 0; q < 4; q++) {
            int fid = tid + NTH * q;
            int e   = fid >> 3;
            int kv  = fid & 7;
            sm[WOFF + (kv * 4 + 0) * WP + e] = pw[q].x;
            sm[WOFF + (kv * 4 + 1) * WP + e] = pw[q].y;
            sm[WOFF + (kv * 4 + 2) * WP + e] = pw[q].z;
            sm[WOFF + (kv * 4 + 3) * WP + e] = pw[q].w;
        }
    };

    auto compute = [&]() {
        u64t chk[2][4];
        #pragma unroll
        for (int k = 0; k < DK; k++) {
            u64t b2[4];
            #pragma unroll
            for (int j = 0; j < 4; j++)
                b2[j] = *reinterpret_cast<const u64t*>(
                            &sm[WOFF + k * WP + 2 * tx + 16 * j]);
            #pragma unroll
            for (int i = 0; i < 2; i++) {
                u64t a2 = *reinterpret_cast<const u64t*>(
                              &h2[(ty + 16 * i) * HP2 + k]);
                if (k == 0) {
                    #pragma unroll
                    for (int j = 0; j < 4; j++) chk[i][j] = mul_f32x2(a2, b2[j]);
                } else {
                    #pragma unroll
                    for (int j = 0; j < 4; j++) fma_f32x2(chk[i][j], a2, b2[j]);
                }
            }
        }
        // merge chunk into totals (blocked summation -> ~2e-7 total error)
        #pragma unroll
        for (int i = 0; i < 2; i++)
            #pragma unroll
            for (int j = 0; j < 4; j++)
                acc[i][j] = add_f32x2(acc[i][j], chk[i][j]);
    };

    const int NC = TDIM / DK;   // 64 chunks
    loadg(0);
    for (int c = 0; c < NC; c++) {
        sts();
        __syncthreads();
        if (c + 1 < NC) loadg((c + 1) * DK);   // overlap next DRAM with compute
        compute();
        __syncthreads();
    }

    // ---- epilogue: calibrate, stage logits to smem (reuses h region) ----
    #pragma unroll
    for (int i = 0; i < 2; i++) {
        int t = ty + 16 * i;
        #pragma unroll
        for (int j = 0; j < 4; j++) {
            int e0 = 2 * tx + 16 * j;
            float lo, hi;
            unpack_f32x2(acc[i][j], lo, hi);
            float l0 = lo * s_cs[e0]     + s_cb[e0];
            float l1 = hi * s_cs[e0 + 1] + s_cb[e0 + 1];
            *reinterpret_cast<float2*>(&sm[t * WP + e0]) = make_float2(l0, l1);
        }
    }
    __syncthreads();

    // ---- per-token softmax + top-8: one thread per token (tid < 32) ----
    if (tid < TM) {
        const int t  = tid;
        const int gt = t0 + t;
        float* row = &sm[t * WP];

        float m = row[0];
        #pragma unroll
        for (int e = 1; e < NEXP; e++) m = fmaxf(m, row[e]);

        float s = 0.f;
        #pragma unroll
        for (int e = 0; e < NEXP; e++) {
            float p = expf(row[e] - m);
            s += p;
            row[e] = p;
        }

        float tv[TOPK];
        int   tix[TOPK];
        #pragma unroll
        for (int r = 0; r < TOPK; r++) { tv[r] = -1.f; tix[r] = 0; }

        float* oprobs = out;                                 // [T,64]
        float* ow     = out + (long long)T * NEXP;           // [T,8]
        float* oi     = ow  + (long long)T * TOPK;           // [T,8] (idx as f32)

        #pragma unroll
        for (int e = 0; e < NEXP; e += 4) {
            // IEEE division (matches reference's exp/sum elementwise divide)
            float p0 = row[e]     / s;
            float p1 = row[e + 1] / s;
            float p2 = row[e + 2] / s;
            float p3 = row[e + 3] / s;
            *reinterpret_cast<float4*>(&oprobs[(long long)gt * NEXP + e]) =
                make_float4(p0, p1, p2, p3);
            TOPK_INSERT(p0, e);
            TOPK_INSERT(p1, e + 1);
            TOPK_INSERT(p2, e + 2);
            TOPK_INSERT(p3, e + 3);
        }

        #pragma unroll
        for (int r = 0; r < TOPK; r++) {
            ow[(long long)gt * TOPK + r] = tv[r];
            oi[(long long)gt * TOPK + r] = (float)tix[r];
        }
    }
}

extern "C" void kernel_launch(void* const* d_in, const int* in_sizes, int n_in,
                              void* d_out, int out_size)
{
    (void)n_in; (void)out_size;
    const float* hs = (const float*)d_in[0];   // hidden_states [4,4096,2048]
    const float* rw = (const float*)d_in[1];   // router_weight [64,2048]
    const float* cs = (const float*)d_in[2];   // cal_scale [64]
    const float* cb = (const float*)d_in[3];   // cal_bias  [64]
    int T = in_sizes[0] / TDIM;                // 16384
    int grid = T / TM;                         // 512 CTAs
    router_gate_kernel<<<grid, NTH>>>(hs, rw, cs, cb, (float*)d_out, T);
}